// round 12
// baseline (speedup 1.0000x reference)
#include <cuda_runtime.h>
#include <cuda_fp16.h>
#include <cuda_bf16.h>

#define NUM_U 200000
#define NUM_I 100000
#define DIM   64
#define KTYP  4
#define NKEYS (2*NUM_U + NUM_I + NUM_U)   // A:200K B:200K C:100K D:200K = 700K
#define CAP   64                          // bucket capacity (Poisson-safe)

#define BASE_A 0
#define BASE_B (NUM_U)
#define BASE_C (2*NUM_U)
#define BASE_D (2*NUM_U + NUM_I)

#define SI ((size_t)NUM_I * 32)

// ---- scratch (device globals; zero-initialized at module load) ----
__device__ __half2 g_ueh[(size_t)KTYP * NUM_U * 32];
__device__ __half2 g_ieh[(size_t)KTYP * NUM_I * 32];
__device__ __half2 g_ub1[(size_t)NUM_U * 32];
__device__ uint4   g_ib1_v[(size_t)KTYP * NUM_I * 8];
__device__ uint4   g_ib2_v[(size_t)KTYP * NUM_I * 8];

__device__ float2  g_pack[(size_t)NKEYS * CAP];   // bucketed packed edges
__device__ int     g_cnt[NKEYS];                  // bucket counts (self-cleaned)

// ---------------------------------------------------------------------------
// Kernels 1+2 — fp32 -> half2 table conversion
// ---------------------------------------------------------------------------
__global__ void convert_kernel(const float2* __restrict__ src,
                               __half2* __restrict__ dst, long long npairs)
{
    long long i = (long long)blockIdx.x * blockDim.x + threadIdx.x;
    if (i < npairs) {
        float2 f = __ldg(src + i);
        dst[i] = __floats2half2_rn(f.x, f.y);
    }
}

// ---------------------------------------------------------------------------
// Kernel 3 — scatter all 6 edge lists into fixed-capacity buckets
//            (no histogram, no scan); tail threads zero ib1/ib2.
// ---------------------------------------------------------------------------
__global__ void scatter_edges(
    const int* __restrict__ u2u_r, const int* __restrict__ u2u_c, const float* __restrict__ u2u_v,
    const int* __restrict__ u2i_r0, const int* __restrict__ u2i_c0, const float* __restrict__ u2i_v0,
    const int* __restrict__ u2i_r1, const int* __restrict__ u2i_c1, const float* __restrict__ u2i_v1,
    const int* __restrict__ i2i_r, const int* __restrict__ i2i_c, const float* __restrict__ i2i_v,
    const int* __restrict__ i2u_r0, const int* __restrict__ i2u_c0, const float* __restrict__ i2u_v0,
    const int* __restrict__ i2u_r1, const int* __restrict__ i2u_c1, const float* __restrict__ i2u_v1,
    int* __restrict__ cnt, float2* __restrict__ pack,
    uint4* __restrict__ zb1, uint4* __restrict__ zb2, long long nzero4,
    int e_uu, int e_ui0, int e_ui1, int e_ii, int e_iu0, int e_iu1)
{
    long long i = (long long)blockIdx.x * blockDim.x + threadIdx.x;
    int key, payload; float val;
    if (i < e_uu) {
        key = BASE_A + __ldg(u2u_r + i); payload = __ldg(u2u_c + i); val = __ldg(u2u_v + i);
    } else if ((i -= e_uu) < e_ui0) {
        key = BASE_B + __ldg(u2i_r0 + i); payload = __ldg(u2i_c0 + i); val = __ldg(u2i_v0 + i);
    } else if ((i -= e_ui0) < e_ui1) {
        key = BASE_B + NUM_U/2 + __ldg(u2i_r1 + i); payload = __ldg(u2i_c1 + i); val = __ldg(u2i_v1 + i);
    } else if ((i -= e_ui1) < e_ii) {
        key = BASE_C + __ldg(i2i_c + i); payload = __ldg(i2i_r + i); val = __ldg(i2i_v + i);
    } else if ((i -= e_ii) < e_iu0) {
        key = BASE_D + __ldg(i2u_c0 + i); payload = __ldg(i2u_r0 + i); val = __ldg(i2u_v0 + i);
    } else if ((i -= e_iu0) < e_iu1) {
        key = BASE_D + __ldg(i2u_c1 + i); payload = __ldg(i2u_r1 + i) + NUM_I/2; val = __ldg(i2u_v1 + i);
    } else {
        i -= e_iu1;
        uint4 z = make_uint4(0, 0, 0, 0);
        if (i < nzero4) zb1[i] = z;
        else if ((i -= nzero4) < nzero4) zb2[i] = z;
        return;
    }
    int slot = atomicAdd(&cnt[key], 1);
    pack[((size_t)key << 6) + slot] = make_float2(__int_as_float(payload), val);
}

// ---------------------------------------------------------------------------
// Gather segment accumulate (2-deep)
// ---------------------------------------------------------------------------
__device__ __forceinline__ void seg_accum(const float2* __restrict__ pack,
                                          const __half2* __restrict__ src,
                                          size_t base, int len, int lane,
                                          float& ax, float& ay)
{
    int i = 0;
    for (; i + 2 <= len; i += 2) {
        float2 p0 = __ldg(pack + base + i);
        float2 p1 = __ldg(pack + base + i + 1);
        float2 v0 = __half22float2(__ldg(src + (size_t)__float_as_int(p0.x) * 32 + lane));
        float2 v1 = __half22float2(__ldg(src + (size_t)__float_as_int(p1.x) * 32 + lane));
        ax = fmaf(p0.y, v0.x, ax); ay = fmaf(p0.y, v0.y, ay);
        ax = fmaf(p1.y, v1.x, ax); ay = fmaf(p1.y, v1.y, ay);
    }
    if (i < len) {
        float2 p = __ldg(pack + base + i);
        float2 v = __half22float2(__ldg(src + (size_t)__float_as_int(p.x) * 32 + lane));
        ax = fmaf(p.y, v.x, ax); ay = fmaf(p.y, v.y, ay);
    }
}

// ---------------------------------------------------------------------------
// Scatter one source column via red.global.add.v4.f16x2
// ---------------------------------------------------------------------------
__device__ __forceinline__ unsigned pk_h2(__half2 h, float v)
{
    float2 f = __half22float2(h);
    __half2 r = __floats2half2_rn(v * f.x, v * f.y);
    return *reinterpret_cast<unsigned*>(&r);
}

__device__ __forceinline__ void scatter_col(int key, const int* __restrict__ cnt,
                                            const float2* __restrict__ pack,
                                            const __half2* __restrict__ src,
                                            __half2* __restrict__ dstbase,
                                            int col, int lane)
{
    int len = __ldg(cnt + key);
    if (len == 0) return;
    size_t base = (size_t)key << 6;
    __half2 rl = __ldg(src + (size_t)col * 32 + lane);
    int j  = lane & 7;
    int ei = lane >> 3;
    __half2 r0 = __shfl_sync(0xffffffffu, rl, 4 * j + 0);
    __half2 r1 = __shfl_sync(0xffffffffu, rl, 4 * j + 1);
    __half2 r2 = __shfl_sync(0xffffffffu, rl, 4 * j + 2);
    __half2 r3 = __shfl_sync(0xffffffffu, rl, 4 * j + 3);
    for (int b = 0; b < len; b += 4) {
        int i = b + ei;
        if (i < len) {
            float2 p = __ldg(pack + base + i);
            int dst = __float_as_int(p.x);
            float v = p.y;
            unsigned q0 = pk_h2(r0, v), q1 = pk_h2(r1, v);
            unsigned q2 = pk_h2(r2, v), q3 = pk_h2(r3, v);
            __half2* ptr = dstbase + (size_t)dst * 32 + 4 * j;
            asm volatile("red.global.add.noftz.v4.f16x2 [%0], {%1,%2,%3,%4};"
                         :: "l"(ptr), "r"(q0), "r"(q1), "r"(q2), "r"(q3)
                         : "memory");
        }
    }
}

// ---------------------------------------------------------------------------
// Layer 1 hybrid: user gather (CSR buckets) + item scatter (CSC buckets).
// ---------------------------------------------------------------------------
#define GU1 25000
#define GS1 37500
#define T1  (GU1 + GS1)

__global__ void __launch_bounds__(256) combined_l1(
    const int* __restrict__ cnt, const float2* __restrict__ pack,
    const __half2* __restrict__ ueh_k, const __half2* __restrict__ ieh_k,
    __half2* __restrict__ ub1, __half2* __restrict__ ib1)
{
    int t = blockIdx.x;
    int warp = threadIdx.x >> 5, lane = threadIdx.x & 31;
    long long lo = (long long)t * GU1 / T1;
    long long hi = (long long)(t + 1) * GU1 / T1;
    if (hi > lo) {
        int w = (int)lo * 8 + warp;
        float ax = 0.0f, ay = 0.0f;
        seg_accum(pack, ueh_k, (size_t)(BASE_A + w) << 6, __ldg(cnt + BASE_A + w), lane, ax, ay);
        seg_accum(pack, ieh_k, (size_t)(BASE_B + w) << 6, __ldg(cnt + BASE_B + w), lane, ax, ay);
        ub1[(size_t)w * 32 + lane] = __floats2half2_rn(ax, ay);
    } else {
        int wg = (t - (int)hi) * 8 + warp;
        if (wg < NUM_I)
            scatter_col(BASE_C + wg, cnt, pack, ieh_k, ib1, wg, lane);
        else
            scatter_col(BASE_D + (wg - NUM_I), cnt, pack, ueh_k, ib1, wg - NUM_I, lane);
    }
}

// ---------------------------------------------------------------------------
// Layer 2 hybrid: user gather + mean + GEMM + ReLU; item scatter -> ib2.
// ---------------------------------------------------------------------------
#define GU2 6250
#define T2  (GU2 + GS1)

__global__ void __launch_bounds__(256) combined_l2(
    const int* __restrict__ cnt, const float2* __restrict__ pack,
    const __half2* __restrict__ ub1, const __half2* __restrict__ ib1,
    __half2* __restrict__ ib2,
    const float* __restrict__ ue0f, const float* __restrict__ W,
    float* __restrict__ out, int out_stride, int out_off)
{
    __shared__ float Ws[DIM][DIM];
    int t = blockIdx.x;
    int warp = threadIdx.x >> 5, lane = threadIdx.x & 31;
    long long lo = (long long)t * GU2 / T2;
    long long hi = (long long)(t + 1) * GU2 / T2;
    if (hi > lo) {
        for (int i = threadIdx.x; i < DIM * DIM; i += blockDim.x)
            Ws[i >> 6][i & 63] = W[i];
        __syncthreads();

        for (int w = (int)lo * 8 + warp; w < NUM_U; w += GU2 * 8) {
            float ax = 0.0f, ay = 0.0f;
            seg_accum(pack, ub1, (size_t)(BASE_A + w) << 6, __ldg(cnt + BASE_A + w), lane, ax, ay);
            seg_accum(pack, ib1, (size_t)(BASE_B + w) << 6, __ldg(cnt + BASE_B + w), lane, ax, ay);

            const float inv3 = 1.0f / 3.0f;
            float2 f0 = __ldg(reinterpret_cast<const float2*>(ue0f + (size_t)w * DIM) + lane);
            float2 f1 = __half22float2(__ldg(ub1 + (size_t)w * 32 + lane));
            float m0 = (f0.x + f1.x + ax) * inv3;
            float m1 = (f0.y + f1.y + ay) * inv3;

            float acc0 = 0.0f, acc1 = 0.0f;
#pragma unroll
            for (int l = 0; l < 32; l++) {
                float b0 = __shfl_sync(0xffffffffu, m0, l);
                float b1 = __shfl_sync(0xffffffffu, m1, l);
                acc0 += b0 * Ws[2 * l][lane]      + b1 * Ws[2 * l + 1][lane];
                acc1 += b0 * Ws[2 * l][lane + 32] + b1 * Ws[2 * l + 1][lane + 32];
            }
            float* o = out + (size_t)w * out_stride + out_off;
            o[lane]      = fmaxf(acc0, 0.0f);
            o[lane + 32] = fmaxf(acc1, 0.0f);
        }
    } else {
        int wg = (t - (int)hi) * 8 + warp;
        if (wg < NUM_I)
            scatter_col(BASE_C + wg, cnt, pack, ib1, ib2, wg, lane);
        else
            scatter_col(BASE_D + (wg - NUM_I), cnt, pack, ub1, ib2, wg - NUM_I, lane);
    }
}

// ---------------------------------------------------------------------------
// Item combine; on the LAST type (do_zero=1) re-zeroes cnt for next replay.
// ---------------------------------------------------------------------------
__global__ void __launch_bounds__(256) item_combine(
    const float* __restrict__ ie0f,
    const __half2* __restrict__ ib1, const __half2* __restrict__ ib2,
    const float* __restrict__ W, float* __restrict__ out,
    int out_stride, int out_off, int* __restrict__ cnt_zero, int do_zero)
{
    __shared__ float Ws[DIM][DIM];
    if (do_zero) {
        for (long long i = (long long)blockIdx.x * blockDim.x + threadIdx.x;
             i < NKEYS; i += (long long)gridDim.x * blockDim.x)
            cnt_zero[i] = 0;
    }

    for (int i = threadIdx.x; i < DIM * DIM; i += blockDim.x)
        Ws[i >> 6][i & 63] = W[i];
    __syncthreads();

    int warp = threadIdx.x >> 5, lane = threadIdx.x & 31;
    for (int w = blockIdx.x * 8 + warp; w < NUM_I; w += gridDim.x * 8) {
        const float inv3 = 1.0f / 3.0f;
        float2 f0 = __ldg(reinterpret_cast<const float2*>(ie0f + (size_t)w * DIM) + lane);
        float2 f1 = __half22float2(__ldg(ib1 + (size_t)w * 32 + lane));
        float2 f2 = __half22float2(__ldg(ib2 + (size_t)w * 32 + lane));
        float m0 = (f0.x + f1.x + f2.x) * inv3;
        float m1 = (f0.y + f1.y + f2.y) * inv3;

        float acc0 = 0.0f, acc1 = 0.0f;
#pragma unroll
        for (int l = 0; l < 32; l++) {
            float b0 = __shfl_sync(0xffffffffu, m0, l);
            float b1 = __shfl_sync(0xffffffffu, m1, l);
            acc0 += b0 * Ws[2 * l][lane]      + b1 * Ws[2 * l + 1][lane];
            acc1 += b0 * Ws[2 * l][lane + 32] + b1 * Ws[2 * l + 1][lane + 32];
        }
        float* o = out + (size_t)w * out_stride + out_off;
        o[lane]      = fmaxf(acc0, 0.0f);
        o[lane + 32] = fmaxf(acc1, 0.0f);
    }
}

// ---------------------------------------------------------------------------
extern "C" void kernel_launch(void* const* d_in, const int* in_sizes, int n_in,
                              void* d_out, int out_size)
{
    const int* u2u_r  = (const int*)d_in[0];  const int* u2u_c  = (const int*)d_in[1];
    const float* u2u_v = (const float*)d_in[2];
    const int* u2i_r0 = (const int*)d_in[3];  const int* u2i_c0 = (const int*)d_in[4];
    const float* u2i_v0 = (const float*)d_in[5];
    const int* u2i_r1 = (const int*)d_in[6];  const int* u2i_c1 = (const int*)d_in[7];
    const float* u2i_v1 = (const float*)d_in[8];
    const int* i2u_r0 = (const int*)d_in[9];  const int* i2u_c0 = (const int*)d_in[10];
    const float* i2u_v0 = (const float*)d_in[11];
    const int* i2u_r1 = (const int*)d_in[12]; const int* i2u_c1 = (const int*)d_in[13];
    const float* i2u_v1 = (const float*)d_in[14];
    const int* i2i_r  = (const int*)d_in[15]; const int* i2i_c  = (const int*)d_in[16];
    const float* i2i_v = (const float*)d_in[17];
    const float* user_embs = (const float*)d_in[18];
    const float* item_embs = (const float*)d_in[19];
    const float* W_u       = (const float*)d_in[20];
    const float* W_v       = (const float*)d_in[21];

    const int e_uu  = in_sizes[0];
    const int e_ui0 = in_sizes[3], e_ui1 = in_sizes[6];
    const int e_iu0 = in_sizes[9], e_iu1 = in_sizes[12];
    const int e_ii  = in_sizes[15];

    float* out_user = (float*)d_out;
    float* out_item = (float*)d_out + (size_t)NUM_U * (KTYP * DIM);

    __half2 *ueh, *ieh, *ub1;
    uint4 *ib1v, *ib2v;
    float2 *pack;
    int *cnt;
    cudaGetSymbolAddress((void**)&ueh, g_ueh);
    cudaGetSymbolAddress((void**)&ieh, g_ieh);
    cudaGetSymbolAddress((void**)&ub1, g_ub1);
    cudaGetSymbolAddress((void**)&ib1v, g_ib1_v);
    cudaGetSymbolAddress((void**)&ib2v, g_ib2_v);
    cudaGetSymbolAddress((void**)&pack, g_pack);
    cudaGetSymbolAddress((void**)&cnt, g_cnt);

    __half2* ib1 = (__half2*)ib1v;
    __half2* ib2 = (__half2*)ib2v;

    // kernels 1+2: table conversion
    {
        long long up = (long long)KTYP * NUM_U * 32;
        long long ip = (long long)KTYP * NUM_I * 32;
        convert_kernel<<<(int)((up + 255) / 256), 256>>>((const float2*)user_embs, ueh, up);
        convert_kernel<<<(int)((ip + 255) / 256), 256>>>((const float2*)item_embs, ieh, ip);
    }

    // kernel 3: bucketed edge scatter + zero ib1/ib2 (cnt is zero on entry)
    {
        long long nzero4 = (long long)KTYP * NUM_I * 8;
        long long total = (long long)e_uu + e_ui0 + e_ui1 + e_ii + e_iu0 + e_iu1
                        + 2 * nzero4;
        scatter_edges<<<(int)((total + 255) / 256), 256>>>(
            u2u_r, u2u_c, u2u_v, u2i_r0, u2i_c0, u2i_v0, u2i_r1, u2i_c1, u2i_v1,
            i2i_r, i2i_c, i2i_v, i2u_r0, i2u_c0, i2u_v0, i2u_r1, i2u_c1, i2u_v1,
            cnt, pack, ib1v, ib2v, nzero4,
            e_uu, e_ui0, e_ui1, e_ii, e_iu0, e_iu1);
    }

    // kernel 4..: main loop (combined_l1 k=0 is kernel #4 -> profiled)
    for (int k = 0; k < KTYP; k++) {
        const float*   ue0f = user_embs + (size_t)k * NUM_U * DIM;
        const float*   ie0f = item_embs + (size_t)k * NUM_I * DIM;
        const __half2* uk   = ueh + (size_t)k * NUM_U * 32;
        const __half2* ik   = ieh + (size_t)k * NUM_I * 32;
        __half2* ib1k = ib1 + (size_t)k * SI;
        __half2* ib2k = ib2 + (size_t)k * SI;

        combined_l1<<<T1, 256>>>(cnt, pack, uk, ik, ub1, ib1k);

        combined_l2<<<T2, 256>>>(cnt, pack, ub1, ib1k, ib2k,
                                 ue0f, W_u + (size_t)k * DIM * DIM,
                                 out_user, KTYP * DIM, k * DIM);

        item_combine<<<3125, 256>>>(ie0f, ib1k, ib2k,
                                    W_v + (size_t)k * DIM * DIM,
                                    out_item, KTYP * DIM, k * DIM,
                                    cnt, (k == KTYP - 1) ? 1 : 0);
    }
}

// round 13
// speedup vs baseline: 1.0438x; 1.0438x over previous
#include <cuda_runtime.h>
#include <cuda_fp16.h>
#include <cuda_bf16.h>

#define NUM_U 200000
#define NUM_I 100000
#define DIM   64
#define KTYP  4
#define NKEYS (2*NUM_U + NUM_I + NUM_U)   // A:200K B:200K C:100K D:200K = 700K
#define NB_SCAN ((NKEYS + 1023) / 1024)   // 684
#define E_TOT 8400000

#define BASE_A 0
#define BASE_B (NUM_U)
#define BASE_C (2*NUM_U)
#define BASE_D (2*NUM_U + NUM_I)

#define SI  ((size_t)NUM_I * 32)   // per-type item stride in half2 units
#define SI4 ((size_t)NUM_I * 8)    // in uint4 units

// ---- scratch (device globals; zero-initialized at module load) ----
// All row-tables declared as uint4 so 16B vector accesses are aligned.
__device__ uint4   g_ueh_v[(size_t)KTYP * NUM_U * 8];
__device__ uint4   g_ieh_v[(size_t)KTYP * NUM_I * 8];
__device__ uint4   g_ub1_v[(size_t)NUM_U * 8];
__device__ uint4   g_ib1_v[(size_t)KTYP * NUM_I * 8];
__device__ uint4   g_ib2_v[(size_t)KTYP * NUM_I * 8];

__device__ float2 g_pack[E_TOT];
__device__ int    g_off[NKEYS + 1];
__device__ int    g_cnt[NKEYS];      // histogram counts; re-zeroed at graph tail
__device__ int    g_cur[NKEYS];      // scatter cursors
__device__ int    g_bsums[NB_SCAN];

// ---------------------------------------------------------------------------
// Op 1 — prep: fp32->half2 conversion + all histograms (cnt zero on entry).
// ---------------------------------------------------------------------------
__global__ void prep_kernel(
    const float2* __restrict__ uemb, const float2* __restrict__ iemb,
    __half2* __restrict__ ueh, __half2* __restrict__ ieh,
    const int* __restrict__ u2u_r,
    const int* __restrict__ u2i_r0, const int* __restrict__ u2i_r1,
    const int* __restrict__ i2i_c,
    const int* __restrict__ i2u_c0, const int* __restrict__ i2u_c1,
    int* __restrict__ cnt,
    int e_uu, int e_ui0, int e_ui1, int e_ii, int e_iu0, int e_iu1)
{
    const long long UCNT = (long long)KTYP * NUM_U * 32;
    const long long ICNT = (long long)KTYP * NUM_I * 32;
    long long i = (long long)blockIdx.x * blockDim.x + threadIdx.x;

    if (i < UCNT) { float2 f = __ldg(uemb + i); ueh[i] = __floats2half2_rn(f.x, f.y); return; }
    i -= UCNT;
    if (i < ICNT) { float2 f = __ldg(iemb + i); ieh[i] = __floats2half2_rn(f.x, f.y); return; }
    i -= ICNT;
    if (i < e_uu)  { atomicAdd(cnt + BASE_A + __ldg(u2u_r  + i), 1); return; }
    i -= e_uu;
    if (i < e_ui0) { atomicAdd(cnt + BASE_B + __ldg(u2i_r0 + i), 1); return; }
    i -= e_ui0;
    if (i < e_ui1) { atomicAdd(cnt + BASE_B + NUM_U/2 + __ldg(u2i_r1 + i), 1); return; }
    i -= e_ui1;
    if (i < e_ii)  { atomicAdd(cnt + BASE_C + __ldg(i2i_c  + i), 1); return; }
    i -= e_ii;
    if (i < e_iu0) { atomicAdd(cnt + BASE_D + __ldg(i2u_c0 + i), 1); return; }
    i -= e_iu0;
    if (i < e_iu1) { atomicAdd(cnt + BASE_D + __ldg(i2u_c1 + i), 1); return; }
}

// ---------------------------------------------------------------------------
// Op 2 — per-tile reduce
// ---------------------------------------------------------------------------
__global__ void __launch_bounds__(1024) scan_reduce(const int* __restrict__ cnt,
                                                    int* __restrict__ bsums)
{
    __shared__ int sh[1024];
    int i = blockIdx.x * 1024 + threadIdx.x;
    sh[threadIdx.x] = (i < NKEYS) ? cnt[i] : 0;
    __syncthreads();
    for (int s = 512; s > 0; s >>= 1) {
        if (threadIdx.x < s) sh[threadIdx.x] += sh[threadIdx.x + s];
        __syncthreads();
    }
    if (threadIdx.x == 0) bsums[blockIdx.x] = sh[0];
}

// ---------------------------------------------------------------------------
// Op 3 — scan+write off[] and cur[]
// ---------------------------------------------------------------------------
__global__ void __launch_bounds__(1024) scan_write(const int* __restrict__ cnt,
                                                   const int* __restrict__ bsums,
                                                   int* __restrict__ off,
                                                   int* __restrict__ cur)
{
    __shared__ int sh[1024];
    __shared__ int s_pref;
    int v = (threadIdx.x < blockIdx.x && threadIdx.x < NB_SCAN) ? bsums[threadIdx.x] : 0;
    sh[threadIdx.x] = v;
    __syncthreads();
    for (int s = 512; s > 0; s >>= 1) {
        if (threadIdx.x < s) sh[threadIdx.x] += sh[threadIdx.x + s];
        __syncthreads();
    }
    if (threadIdx.x == 0) s_pref = sh[0];
    __syncthreads();

    int i = blockIdx.x * 1024 + threadIdx.x;
    int c = (i < NKEYS) ? cnt[i] : 0;
    sh[threadIdx.x] = c;
    __syncthreads();
    for (int d = 1; d < 1024; d <<= 1) {
        int t = (threadIdx.x >= d) ? sh[threadIdx.x - d] : 0;
        __syncthreads();
        sh[threadIdx.x] += t;
        __syncthreads();
    }
    int excl = s_pref + sh[threadIdx.x] - c;
    if (i < NKEYS) { off[i] = excl; cur[i] = excl; }
    if (i == NKEYS - 1) off[NKEYS] = excl + c;
}

// ---------------------------------------------------------------------------
// Op 4 — scatter all 6 edge lists into compact pack; tail zeroes ib1/ib2.
// ---------------------------------------------------------------------------
__global__ void scatter_edges(
    const int* __restrict__ u2u_r, const int* __restrict__ u2u_c, const float* __restrict__ u2u_v,
    const int* __restrict__ u2i_r0, const int* __restrict__ u2i_c0, const float* __restrict__ u2i_v0,
    const int* __restrict__ u2i_r1, const int* __restrict__ u2i_c1, const float* __restrict__ u2i_v1,
    const int* __restrict__ i2i_r, const int* __restrict__ i2i_c, const float* __restrict__ i2i_v,
    const int* __restrict__ i2u_r0, const int* __restrict__ i2u_c0, const float* __restrict__ i2u_v0,
    const int* __restrict__ i2u_r1, const int* __restrict__ i2u_c1, const float* __restrict__ i2u_v1,
    int* __restrict__ cur, float2* __restrict__ pack,
    uint4* __restrict__ zb1, uint4* __restrict__ zb2, long long nzero4,
    int e_uu, int e_ui0, int e_ui1, int e_ii, int e_iu0, int e_iu1)
{
    long long i = (long long)blockIdx.x * blockDim.x + threadIdx.x;
    int key, payload; float val;
    if (i < e_uu) {
        key = BASE_A + __ldg(u2u_r + i); payload = __ldg(u2u_c + i); val = __ldg(u2u_v + i);
    } else if ((i -= e_uu) < e_ui0) {
        key = BASE_B + __ldg(u2i_r0 + i); payload = __ldg(u2i_c0 + i); val = __ldg(u2i_v0 + i);
    } else if ((i -= e_ui0) < e_ui1) {
        key = BASE_B + NUM_U/2 + __ldg(u2i_r1 + i); payload = __ldg(u2i_c1 + i); val = __ldg(u2i_v1 + i);
    } else if ((i -= e_ui1) < e_ii) {
        key = BASE_C + __ldg(i2i_c + i); payload = __ldg(i2i_r + i); val = __ldg(i2i_v + i);
    } else if ((i -= e_ii) < e_iu0) {
        key = BASE_D + __ldg(i2u_c0 + i); payload = __ldg(i2u_r0 + i); val = __ldg(i2u_v0 + i);
    } else if ((i -= e_iu0) < e_iu1) {
        key = BASE_D + __ldg(i2u_c1 + i); payload = __ldg(i2u_r1 + i) + NUM_I/2; val = __ldg(i2u_v1 + i);
    } else {
        i -= e_iu1;
        uint4 z = make_uint4(0, 0, 0, 0);
        if (i < nzero4) zb1[i] = z;
        else if ((i -= nzero4) < nzero4) zb2[i] = z;
        return;
    }
    int pos = atomicAdd(&cur[key], 1);
    pack[pos] = make_float2(__int_as_float(payload), val);
}

// ---------------------------------------------------------------------------
// Instruction-lean gather: warp-per-row, 4 edges/iter.
// Lane = (ei, j): ei = lane>>3 edge slot, j = lane&7 owns 16B of the row.
// ---------------------------------------------------------------------------
__device__ __forceinline__ void gather_row(const float2* __restrict__ pack,
                                           const uint4* __restrict__ src4,
                                           int s, int e, int ei, int j,
                                           float2 acc[4])
{
    for (int i = s + ei; i < e; i += 4) {
        float2 p = __ldg(pack + i);
        uint4 q = __ldg(src4 + (size_t)__float_as_int(p.x) * 8 + j);
        float pv = p.y;
        float2 v0 = __half22float2(*reinterpret_cast<__half2*>(&q.x));
        float2 v1 = __half22float2(*reinterpret_cast<__half2*>(&q.y));
        float2 v2 = __half22float2(*reinterpret_cast<__half2*>(&q.z));
        float2 v3 = __half22float2(*reinterpret_cast<__half2*>(&q.w));
        acc[0].x = fmaf(pv, v0.x, acc[0].x); acc[0].y = fmaf(pv, v0.y, acc[0].y);
        acc[1].x = fmaf(pv, v1.x, acc[1].x); acc[1].y = fmaf(pv, v1.y, acc[1].y);
        acc[2].x = fmaf(pv, v2.x, acc[2].x); acc[2].y = fmaf(pv, v2.y, acc[2].y);
        acc[3].x = fmaf(pv, v3.x, acc[3].x); acc[3].y = fmaf(pv, v3.y, acc[3].y);
    }
}

// Butterfly-sum across the 4 ei groups (all lanes end with the full sum).
__device__ __forceinline__ void reduce_ei(float2 acc[4])
{
#pragma unroll
    for (int m = 8; m <= 16; m <<= 1) {
#pragma unroll
        for (int k = 0; k < 4; k++) {
            acc[k].x += __shfl_xor_sync(0xffffffffu, acc[k].x, m);
            acc[k].y += __shfl_xor_sync(0xffffffffu, acc[k].y, m);
        }
    }
}

// ---------------------------------------------------------------------------
// Scatter one source column via red.global.add.v4.f16x2 (uint4 preload).
// ---------------------------------------------------------------------------
__device__ __forceinline__ unsigned pk_f2(float2 f, float v)
{
    __half2 r = __floats2half2_rn(v * f.x, v * f.y);
    return *reinterpret_cast<unsigned*>(&r);
}

__device__ __forceinline__ void scatter_col(int key,
                                            const int* __restrict__ off,
                                            const float2* __restrict__ pack,
                                            const uint4* __restrict__ src4,
                                            __half2* __restrict__ dstbase,
                                            int col, int lane)
{
    int s = __ldg(off + key), e = __ldg(off + key + 1);
    if (s == e) return;
    int j  = lane & 7;
    int ei = lane >> 3;
    uint4 q = __ldg(src4 + (size_t)col * 8 + j);
    float2 f0 = __half22float2(*reinterpret_cast<__half2*>(&q.x));
    float2 f1 = __half22float2(*reinterpret_cast<__half2*>(&q.y));
    float2 f2 = __half22float2(*reinterpret_cast<__half2*>(&q.z));
    float2 f3 = __half22float2(*reinterpret_cast<__half2*>(&q.w));
    for (int i = s + ei; i < e; i += 4) {
        float2 p = __ldg(pack + i);
        int dst = __float_as_int(p.x);
        float v = p.y;
        unsigned q0 = pk_f2(f0, v), q1 = pk_f2(f1, v);
        unsigned q2 = pk_f2(f2, v), q3 = pk_f2(f3, v);
        __half2* ptr = dstbase + (size_t)dst * 32 + 4 * j;
        asm volatile("red.global.add.noftz.v4.f16x2 [%0], {%1,%2,%3,%4};"
                     :: "l"(ptr), "r"(q0), "r"(q1), "r"(q2), "r"(q3)
                     : "memory");
    }
}

// ---------------------------------------------------------------------------
// Layer 1 hybrid: user gather (lean) + item scatter, role-interleaved.
// ---------------------------------------------------------------------------
#define GU1 25000
#define GS1 37500
#define T1  (GU1 + GS1)

__global__ void __launch_bounds__(256) combined_l1(
    const int* __restrict__ off, const float2* __restrict__ pack,
    const uint4* __restrict__ ueh4_k, const uint4* __restrict__ ieh4_k,
    uint4* __restrict__ ub1v, __half2* __restrict__ ib1)
{
    int t = blockIdx.x;
    int warp = threadIdx.x >> 5, lane = threadIdx.x & 31;
    long long lo = (long long)t * GU1 / T1;
    long long hi = (long long)(t + 1) * GU1 / T1;
    if (hi > lo) {
        int w = (int)lo * 8 + warp;
        int ei = lane >> 3, j = lane & 7;
        float2 acc[4] = {{0,0},{0,0},{0,0},{0,0}};
        gather_row(pack, ueh4_k, __ldg(off + BASE_A + w), __ldg(off + BASE_A + w + 1), ei, j, acc);
        gather_row(pack, ieh4_k, __ldg(off + BASE_B + w), __ldg(off + BASE_B + w + 1), ei, j, acc);
        reduce_ei(acc);
        if (ei == 0) {
            uint4 o;
            *reinterpret_cast<__half2*>(&o.x) = __floats2half2_rn(acc[0].x, acc[0].y);
            *reinterpret_cast<__half2*>(&o.y) = __floats2half2_rn(acc[1].x, acc[1].y);
            *reinterpret_cast<__half2*>(&o.z) = __floats2half2_rn(acc[2].x, acc[2].y);
            *reinterpret_cast<__half2*>(&o.w) = __floats2half2_rn(acc[3].x, acc[3].y);
            ub1v[(size_t)w * 8 + j] = o;
        }
    } else {
        int wg = (t - (int)hi) * 8 + warp;
        if (wg < NUM_I)
            scatter_col(BASE_C + wg, off, pack, ieh4_k, ib1, wg, lane);
        else
            scatter_col(BASE_D + (wg - NUM_I), off, pack,
                        (const uint4*)ueh4_k, ib1, wg - NUM_I, lane);
    }
}

// ---------------------------------------------------------------------------
// Layer 2 hybrid: lean user gather + mean + GEMM + ReLU; item scatter -> ib2.
// ---------------------------------------------------------------------------
#define GU2 6250
#define T2  (GU2 + GS1)

__global__ void __launch_bounds__(256) combined_l2(
    const int* __restrict__ off, const float2* __restrict__ pack,
    const uint4* __restrict__ ub1v, const uint4* __restrict__ ib1v,
    __half2* __restrict__ ib2,
    const float* __restrict__ ue0f, const float* __restrict__ W,
    float* __restrict__ out, int out_stride, int out_off)
{
    __shared__ float Ws[DIM][DIM];
    int t = blockIdx.x;
    int warp = threadIdx.x >> 5, lane = threadIdx.x & 31;
    long long lo = (long long)t * GU2 / T2;
    long long hi = (long long)(t + 1) * GU2 / T2;
    if (hi > lo) {
        for (int i = threadIdx.x; i < DIM * DIM; i += blockDim.x)
            Ws[i >> 6][i & 63] = W[i];
        __syncthreads();

        const __half2* ub1 = (const __half2*)ub1v;
        int ei = lane >> 3, j = lane & 7;

        for (int w = (int)lo * 8 + warp; w < NUM_U; w += GU2 * 8) {
            float2 acc[4] = {{0,0},{0,0},{0,0},{0,0}};
            gather_row(pack, ub1v, __ldg(off + BASE_A + w), __ldg(off + BASE_A + w + 1), ei, j, acc);
            gather_row(pack, ib1v, __ldg(off + BASE_B + w), __ldg(off + BASE_B + w + 1), ei, j, acc);
            reduce_ei(acc);

            // redistribute: lane l takes dims (2l, 2l+1) from lane l>>2, pair l&3
            float gx = 0.0f, gy = 0.0f;
            int srcl = lane >> 2;
#pragma unroll
            for (int p = 0; p < 4; p++) {
                float tx = __shfl_sync(0xffffffffu, acc[p].x, srcl);
                float ty = __shfl_sync(0xffffffffu, acc[p].y, srcl);
                if ((lane & 3) == p) { gx = tx; gy = ty; }
            }

            const float inv3 = 1.0f / 3.0f;
            float2 f0 = __ldg(reinterpret_cast<const float2*>(ue0f + (size_t)w * DIM) + lane);
            float2 f1 = __half22float2(__ldg(ub1 + (size_t)w * 32 + lane));
            float m0 = (f0.x + f1.x + gx) * inv3;
            float m1 = (f0.y + f1.y + gy) * inv3;

            float acc0 = 0.0f, acc1 = 0.0f;
#pragma unroll
            for (int l = 0; l < 32; l++) {
                float b0 = __shfl_sync(0xffffffffu, m0, l);
                float b1 = __shfl_sync(0xffffffffu, m1, l);
                acc0 += b0 * Ws[2 * l][lane]      + b1 * Ws[2 * l + 1][lane];
                acc1 += b0 * Ws[2 * l][lane + 32] + b1 * Ws[2 * l + 1][lane + 32];
            }
            float* o = out + (size_t)w * out_stride + out_off;
            o[lane]      = fmaxf(acc0, 0.0f);
            o[lane + 32] = fmaxf(acc1, 0.0f);
        }
    } else {
        int wg = (t - (int)hi) * 8 + warp;
        if (wg < NUM_I)
            scatter_col(BASE_C + wg, off, pack, ib1v, ib2, wg, lane);
        else
            scatter_col(BASE_D + (wg - NUM_I), off, pack, ub1v, ib2, wg - NUM_I, lane);
    }
}

// ---------------------------------------------------------------------------
// Item combine + tail re-zero of cnt (self-cleaning graph).
// ---------------------------------------------------------------------------
__global__ void __launch_bounds__(256) item_combine(
    const float* __restrict__ ie0f,
    const __half2* __restrict__ ib1, const __half2* __restrict__ ib2,
    const float* __restrict__ W, float* __restrict__ out,
    int out_stride, int out_off, int* __restrict__ cnt_zero)
{
    __shared__ float Ws[DIM][DIM];
    for (long long i = (long long)blockIdx.x * blockDim.x + threadIdx.x;
         i < NKEYS; i += (long long)gridDim.x * blockDim.x)
        cnt_zero[i] = 0;

    for (int i = threadIdx.x; i < DIM * DIM; i += blockDim.x)
        Ws[i >> 6][i & 63] = W[i];
    __syncthreads();

    int warp = threadIdx.x >> 5, lane = threadIdx.x & 31;
    for (int w = blockIdx.x * 8 + warp; w < NUM_I; w += gridDim.x * 8) {
        const float inv3 = 1.0f / 3.0f;
        float2 f0 = __ldg(reinterpret_cast<const float2*>(ie0f + (size_t)w * DIM) + lane);
        float2 f1 = __half22float2(__ldg(ib1 + (size_t)w * 32 + lane));
        float2 f2 = __half22float2(__ldg(ib2 + (size_t)w * 32 + lane));
        float m0 = (f0.x + f1.x + f2.x) * inv3;
        float m1 = (f0.y + f1.y + f2.y) * inv3;

        float acc0 = 0.0f, acc1 = 0.0f;
#pragma unroll
        for (int l = 0; l < 32; l++) {
            float b0 = __shfl_sync(0xffffffffu, m0, l);
            float b1 = __shfl_sync(0xffffffffu, m1, l);
            acc0 += b0 * Ws[2 * l][lane]      + b1 * Ws[2 * l + 1][lane];
            acc1 += b0 * Ws[2 * l][lane + 32] + b1 * Ws[2 * l + 1][lane + 32];
        }
        float* o = out + (size_t)w * out_stride + out_off;
        o[lane]      = fmaxf(acc0, 0.0f);
        o[lane + 32] = fmaxf(acc1, 0.0f);
    }
}

// ---------------------------------------------------------------------------
extern "C" void kernel_launch(void* const* d_in, const int* in_sizes, int n_in,
                              void* d_out, int out_size)
{
    const int* u2u_r  = (const int*)d_in[0];  const int* u2u_c  = (const int*)d_in[1];
    const float* u2u_v = (const float*)d_in[2];
    const int* u2i_r0 = (const int*)d_in[3];  const int* u2i_c0 = (const int*)d_in[4];
    const float* u2i_v0 = (const float*)d_in[5];
    const int* u2i_r1 = (const int*)d_in[6];  const int* u2i_c1 = (const int*)d_in[7];
    const float* u2i_v1 = (const float*)d_in[8];
    const int* i2u_r0 = (const int*)d_in[9];  const int* i2u_c0 = (const int*)d_in[10];
    const float* i2u_v0 = (const float*)d_in[11];
    const int* i2u_r1 = (const int*)d_in[12]; const int* i2u_c1 = (const int*)d_in[13];
    const float* i2u_v1 = (const float*)d_in[14];
    const int* i2i_r  = (const int*)d_in[15]; const int* i2i_c  = (const int*)d_in[16];
    const float* i2i_v = (const float*)d_in[17];
    const float* user_embs = (const float*)d_in[18];
    const float* item_embs = (const float*)d_in[19];
    const float* W_u       = (const float*)d_in[20];
    const float* W_v       = (const float*)d_in[21];

    const int e_uu  = in_sizes[0];
    const int e_ui0 = in_sizes[3], e_ui1 = in_sizes[6];
    const int e_iu0 = in_sizes[9], e_iu1 = in_sizes[12];
    const int e_ii  = in_sizes[15];

    float* out_user = (float*)d_out;
    float* out_item = (float*)d_out + (size_t)NUM_U * (KTYP * DIM);

    uint4 *ueh4, *ieh4, *ub1v, *ib1v, *ib2v;
    float2 *pack;
    int *off, *cnt, *cur, *bs;
    cudaGetSymbolAddress((void**)&ueh4, g_ueh_v);
    cudaGetSymbolAddress((void**)&ieh4, g_ieh_v);
    cudaGetSymbolAddress((void**)&ub1v, g_ub1_v);
    cudaGetSymbolAddress((void**)&ib1v, g_ib1_v);
    cudaGetSymbolAddress((void**)&ib2v, g_ib2_v);
    cudaGetSymbolAddress((void**)&pack, g_pack);
    cudaGetSymbolAddress((void**)&off, g_off);
    cudaGetSymbolAddress((void**)&cnt, g_cnt);
    cudaGetSymbolAddress((void**)&cur, g_cur);
    cudaGetSymbolAddress((void**)&bs, g_bsums);

    // op 1: prep (convert + histogram)
    {
        long long total = (long long)KTYP * NUM_U * 32 + (long long)KTYP * NUM_I * 32
                        + e_uu + e_ui0 + e_ui1 + e_ii + e_iu0 + e_iu1;
        prep_kernel<<<(int)((total + 255) / 256), 256>>>(
            (const float2*)user_embs, (const float2*)item_embs,
            (__half2*)ueh4, (__half2*)ieh4,
            u2u_r, u2i_r0, u2i_r1, i2i_c, i2u_c0, i2u_c1,
            cnt, e_uu, e_ui0, e_ui1, e_ii, e_iu0, e_iu1);
    }

    // ops 2+3: scan
    scan_reduce<<<NB_SCAN, 1024>>>(cnt, bs);
    scan_write<<<NB_SCAN, 1024>>>(cnt, bs, off, cur);

    // op 4: scatter edges + zero ib1/ib2
    {
        long long nzero4 = (long long)KTYP * NUM_I * 8;
        long long total = (long long)e_uu + e_ui0 + e_ui1 + e_ii + e_iu0 + e_iu1
                        + 2 * nzero4;
        scatter_edges<<<(int)((total + 255) / 256), 256>>>(
            u2u_r, u2u_c, u2u_v, u2i_r0, u2i_c0, u2i_v0, u2i_r1, u2i_c1, u2i_v1,
            i2i_r, i2i_c, i2i_v, i2u_r0, i2u_c0, i2u_v0, i2u_r1, i2u_c1, i2u_v1,
            cur, pack, ib1v, ib2v, nzero4,
            e_uu, e_ui0, e_ui1, e_ii, e_iu0, e_iu1);
    }

    // main loop: type-sequential
    for (int k = 0; k < KTYP; k++) {
        const float* ue0f = user_embs + (size_t)k * NUM_U * DIM;
        const float* ie0f = item_embs + (size_t)k * NUM_I * DIM;
        const uint4* uk4  = ueh4 + (size_t)k * NUM_U * 8;
        const uint4* ik4  = ieh4 + (size_t)k * NUM_I * 8;
        uint4* ib1k = ib1v + (size_t)k * SI4;
        uint4* ib2k = ib2v + (size_t)k * SI4;

        combined_l1<<<T1, 256>>>(off, pack, uk4, ik4, ub1v, (__half2*)ib1k);

        combined_l2<<<T2, 256>>>(off, pack, ub1v, ib1k, (__half2*)ib2k,
                                 ue0f, W_u + (size_t)k * DIM * DIM,
                                 out_user, KTYP * DIM, k * DIM);

        item_combine<<<3125, 256>>>(ie0f, (const __half2*)ib1k, (const __half2*)ib2k,
                                    W_v + (size_t)k * DIM * DIM,
                                    out_item, KTYP * DIM, k * DIM, cnt);
    }
}